// round 14
// baseline (speedup 1.0000x reference)
#include <cuda_runtime.h>
#include <cuda_fp16.h>
#include <math.h>
#include <stdint.h>

// ---------------- problem constants ----------------
#define BB   2
#define TT   2048
#define HH   16
#define SS   64
#define EMB  1024          // HH*SS
#define ROWS (BB*TT)       // 4096
#define FF4  (4*EMB)       // 4096

// ---------------- scratch (device globals; no allocation) ----------------
__device__ __half g_xh [(long long)ROWS * EMB];      // x in fp16
__device__ __half g_kqv[(long long)ROWS * HH * 192]; // [B,T,H,192] (k|q|v) fp16
__device__ __half g_res[(long long)ROWS * EMB];      // attention out (fp16)
__device__ float  g_mha[(long long)ROWS * EMB];
__device__ float  g_x1 [(long long)ROWS * EMB];
__device__ __half g_x1h[(long long)ROWS * EMB];
__device__ __half g_hh [(long long)ROWS * FF4];
__device__ float  g_ff [(long long)ROWS * EMB];
// fp16 weights, k-major [K, N]
__device__ __half g_Wkh[(long long)SS * 192];
__device__ __half g_Wph[(long long)EMB * EMB];
__device__ __half g_W1h[(long long)EMB * FF4];
__device__ __half g_W2h[(long long)FF4 * EMB];

// ---------------- helpers ----------------
__device__ __forceinline__ float gelu_exact(float v) {
    return 0.5f * v * (1.0f + erff(v * 0.70710678118654752440f));
}
__device__ __forceinline__ void mma_f16(float (&d)[4], const uint32_t (&a)[4],
                                        const uint32_t b0, const uint32_t b1,
                                        const float (&c)[4]) {
    asm volatile(
        "mma.sync.aligned.m16n8k16.row.col.f32.f16.f16.f32 "
        "{%0,%1,%2,%3}, {%4,%5,%6,%7}, {%8,%9}, {%10,%11,%12,%13};\n"
        : "=f"(d[0]), "=f"(d[1]), "=f"(d[2]), "=f"(d[3])
        : "r"(a[0]), "r"(a[1]), "r"(a[2]), "r"(a[3]),
          "r"(b0), "r"(b1),
          "f"(c[0]), "f"(c[1]), "f"(c[2]), "f"(c[3]));
}
__device__ __forceinline__ uint32_t pack2(float lo, float hi) {
    __half2 h = __floats2half2_rn(lo, hi);
    return *(uint32_t*)&h;
}
__device__ __forceinline__ uint32_t smem_u32(const void* p) {
    uint32_t a;
    asm("{ .reg .u64 t; cvta.to.shared.u64 t, %1; cvt.u32.u64 %0, t; }" : "=r"(a) : "l"(p));
    return a;
}
__device__ __forceinline__ void cp16(uint32_t dst, const void* src) {
    asm volatile("cp.async.cg.shared.global [%0], [%1], 16;" :: "r"(dst), "l"(src));
}
__device__ __forceinline__ void cp_commit() {
    asm volatile("cp.async.commit_group;" ::: "memory");
}
template<int N>
__device__ __forceinline__ void cp_wait() {
    asm volatile("cp.async.wait_group %0;" :: "n"(N) : "memory");
}
__device__ __forceinline__ void ldm_x4(uint32_t& r0, uint32_t& r1, uint32_t& r2,
                                       uint32_t& r3, uint32_t addr) {
    asm volatile("ldmatrix.sync.aligned.m8n8.x4.shared.b16 {%0,%1,%2,%3}, [%4];"
                 : "=r"(r0), "=r"(r1), "=r"(r2), "=r"(r3) : "r"(addr));
}
__device__ __forceinline__ void ldm_x4_t(uint32_t& r0, uint32_t& r1, uint32_t& r2,
                                         uint32_t& r3, uint32_t addr) {
    asm volatile("ldmatrix.sync.aligned.m8n8.x4.trans.shared.b16 {%0,%1,%2,%3}, [%4];"
                 : "=r"(r0), "=r"(r1), "=r"(r2), "=r"(r3) : "r"(addr));
}

// ================= fp16 GEMM: 64x64 warp tiles, B k-major =================
// C[M,N] = A[M,K] @ B[K,N].  BM=128, BK=64, BN in {64,128,256}.
// BN=256: 8 warps (2m x 4n); BN<=128: 4 warps (2m x 2n). Warp tile 64 x WN.
// EPI: 0 = f32; 1 = +bias f32; 2 = +bias+gelu f16; 3 = plain f16.
template<int BN, int EPI>
__global__ __launch_bounds__(BN == 256 ? 256 : 128)
void gemm_f16(const __half* __restrict__ Ah, const __half* __restrict__ Bw,
              const float* __restrict__ bias,
              float* __restrict__ Cf, __half* __restrict__ Ch,
              int M, int N, int K)
{
    constexpr int BM = 128, BK = 64;
    constexpr int WARPSN = (BN == 256) ? 4 : 2;
    constexpr int THREADS = 64 * WARPSN;    // 256 or 128
    constexpr int WN  = BN / WARPSN;        // 64 or 32
    constexpr int NT  = WN / 8;             // n8 tiles per warp
    constexpr int NP  = NT / 2;             // 16-col pairs
    constexpr int LDA = 72;                 // A row stride (halves)
    constexpr int LDB = BN + 8;             // B row stride (halves)
    constexpr int ABY = BM * LDA * 2;       // 18432
    constexpr int BBY = BK * LDB * 2;
    constexpr int STB = ABY + BBY;
    constexpr int CPR = BN / 8;             // B 16B-chunks per row
    constexpr int ACH = (BM * BK / 8) / THREADS;   // A chunks per thread
    constexpr int BCH = (BK * CPR) / THREADS;      // B chunks per thread

    extern __shared__ char smc[];
    const uint32_t sbase = smem_u32(smc);

    const int tid  = threadIdx.x;
    const int w    = tid >> 5;
    const int lane = tid & 31;
    const int g    = lane >> 2;
    const int t4   = lane & 3;
    const int wm   = w / WARPSN;            // 0..1
    const int wn   = w % WARPSN;
    const int m0   = blockIdx.y * BM;
    const int n0   = blockIdx.x * BN;

    float acc[4][NT][4];
    #pragma unroll
    for (int mt = 0; mt < 4; mt++)
        #pragma unroll
        for (int nt = 0; nt < NT; nt++)
            #pragma unroll
            for (int i = 0; i < 4; i++) acc[mt][nt][i] = 0.f;

    const int nk = K >> 6;   // BK=64 slabs

    auto load_slab = [&](int kt, int st) {
        const uint32_t sa = sbase + (uint32_t)st * STB;
        #pragma unroll
        for (int i = 0; i < ACH; i++) {
            int ci = tid + i * THREADS;
            int r = ci >> 3, c = (ci & 7) * 8;
            cp16(sa + (uint32_t)(r * LDA + c) * 2,
                 Ah + (long long)(m0 + r) * K + kt * 64 + c);
        }
        const uint32_t sb = sa + ABY;
        #pragma unroll
        for (int i = 0; i < BCH; i++) {
            int ci = tid + i * THREADS;
            int r = ci / CPR, c = (ci % CPR) * 8;
            cp16(sb + (uint32_t)(r * LDB + c) * 2,
                 Bw + (long long)(kt * 64 + r) * N + n0 + c);
        }
        cp_commit();
    };

    // per-lane ldmatrix base offsets (bytes)
    const uint32_t aoff = (uint32_t)((wm * 64 + (lane & 15)) * LDA + (lane >> 4) * 8) * 2;
    const uint32_t boff = (uint32_t)((lane & 15) * LDB * 2 + (lane >> 4) * 16 + wn * WN * 2);

    load_slab(0, 0);

    for (int kt = 0; kt < nk; ++kt) {
        cp_wait<0>();
        __syncthreads();
        if (kt + 1 < nk) load_slab(kt + 1, (kt + 1) & 1);

        const uint32_t sa = sbase + (uint32_t)(kt & 1) * STB;
        const uint32_t sb = sa + ABY;
        #pragma unroll
        for (int ks = 0; ks < 4; ks++) {
            uint32_t a[4][4];
            #pragma unroll
            for (int mt = 0; mt < 4; mt++)
                ldm_x4(a[mt][0], a[mt][1], a[mt][2], a[mt][3],
                       sa + aoff + (uint32_t)(mt * (16 * LDA * 2) + ks * 32));
            #pragma unroll
            for (int np = 0; np < NP; np++) {
                uint32_t r0, r1, r2, r3;
                ldm_x4_t(r0, r1, r2, r3,
                         sb + boff + (uint32_t)(ks * (16 * LDB * 2) + np * 32));
                #pragma unroll
                for (int mt = 0; mt < 4; mt++) {
                    mma_f16(acc[mt][2 * np],     a[mt], r0, r1, acc[mt][2 * np]);
                    mma_f16(acc[mt][2 * np + 1], a[mt], r2, r3, acc[mt][2 * np + 1]);
                }
            }
        }
    }

    // epilogue
    #pragma unroll
    for (int mt = 0; mt < 4; mt++) {
        int row = m0 + wm * 64 + mt * 16 + g;
        #pragma unroll
        for (int nt = 0; nt < NT; nt++) {
            int col = n0 + wn * WN + nt * 8 + 2 * t4;
            float v00 = acc[mt][nt][0], v01 = acc[mt][nt][1];
            float v10 = acc[mt][nt][2], v11 = acc[mt][nt][3];
            if (EPI == 1 || EPI == 2) {
                float b0 = bias[col], b1 = bias[col + 1];
                v00 += b0; v01 += b1; v10 += b0; v11 += b1;
            }
            if (EPI == 2) {
                v00 = gelu_exact(v00); v01 = gelu_exact(v01);
                v10 = gelu_exact(v10); v11 = gelu_exact(v11);
            }
            const long long o0 = (long long)row * N + col;
            const long long o1 = (long long)(row + 8) * N + col;
            if (EPI == 2 || EPI == 3) {
                *(uint32_t*)(Ch + o0) = pack2(v00, v01);
                *(uint32_t*)(Ch + o1) = pack2(v10, v11);
            } else {
                *(float2*)(Cf + o0) = make_float2(v00, v01);
                *(float2*)(Cf + o1) = make_float2(v10, v11);
            }
        }
    }
}

// ============ fused f32 -> fp16 conversions (one launch for all) ============
// segment sizes in 1024-element blocks
#define NB_X  ((ROWS * EMB) / 1024)        // 4096
#define NB_WK ((SS * 192) / 1024)          // 12
#define NB_WP ((EMB * EMB) / 1024)         // 1024
#define NB_W1 ((EMB * FF4) / 1024)         // 4096
#define NB_W2 ((FF4 * EMB) / 1024)         // 4096
__global__ __launch_bounds__(256)
void cvt_all(const float* __restrict__ x, const float* __restrict__ Wk,
             const float* __restrict__ Wp, const float* __restrict__ W1,
             const float* __restrict__ W2,
             __half* __restrict__ xh, __half* __restrict__ Wkh,
             __half* __restrict__ Wph, __half* __restrict__ W1h,
             __half* __restrict__ W2h)
{
    int blk = blockIdx.x;
    const float* src; __half* dst;
    if      (blk < NB_X)                         { src = x;  dst = xh; }
    else if ((blk -= NB_X)  < NB_WK)             { src = Wk; dst = Wkh; }
    else if ((blk -= NB_WK) < NB_WP)             { src = Wp; dst = Wph; }
    else if ((blk -= NB_WP) < NB_W1)             { src = W1; dst = W1h; }
    else    { blk -= NB_W1;                        src = W2; dst = W2h; }
    const long long i = ((long long)blk * 256 + threadIdx.x) * 4;
    float4 v = *(const float4*)(src + i);
    __half h[4] = {__float2half_rn(v.x), __float2half_rn(v.y),
                   __float2half_rn(v.z), __float2half_rn(v.w)};
    *(uint2*)(dst + i) = *(uint2*)h;
}

// ================= fp16 flash attention: cp.async + ldmatrix =================
// grid (T/128, H, B), 256 threads = 8 warps; warp w owns 16 query rows.
__global__ __launch_bounds__(256)
void attn_f16(const __half* __restrict__ kqv, __half* __restrict__ res)
{
    __shared__ __half Ks[2][64][72];   // [key][dim]
    __shared__ __half Vs[2][64][72];   // [key][dim] raw; transposed via ldmatrix.trans

    const int tid  = threadIdx.x;
    const int w    = tid >> 5;
    const int lane = tid & 31;
    const int g    = lane >> 2;
    const int t4   = lane & 3;
    const int b    = blockIdx.z;
    const int h    = blockIdx.y;
    const int q0   = blockIdx.x * 128 + w * 16;

    const long long rowstride = (long long)HH * 192;
    const __half* base = kqv + ((long long)b * TT * HH + h) * 192;

    // Q A-frags, pre-scaled by 1/sqrt(S) = 0.125 (exact in fp16)
    uint32_t qf[4][4];
    {
        const __half2 sc = __float2half2_rn(0.125f);
        const __half* qp0 = base + (long long)(q0 + g)     * rowstride + 64;
        const __half* qp1 = base + (long long)(q0 + 8 + g) * rowstride + 64;
        #pragma unroll
        for (int kk = 0; kk < 4; kk++) {
            __half2 v0 = __hmul2(*(const __half2*)(qp0 + kk * 16 + 2 * t4), sc);
            __half2 v1 = __hmul2(*(const __half2*)(qp1 + kk * 16 + 2 * t4), sc);
            __half2 v2 = __hmul2(*(const __half2*)(qp0 + kk * 16 + 2 * t4 + 8), sc);
            __half2 v3 = __hmul2(*(const __half2*)(qp1 + kk * 16 + 2 * t4 + 8), sc);
            qf[kk][0] = *(uint32_t*)&v0; qf[kk][1] = *(uint32_t*)&v1;
            qf[kk][2] = *(uint32_t*)&v2; qf[kk][3] = *(uint32_t*)&v3;
        }
    }

    const uint32_t ks_base = smem_u32(&Ks[0][0][0]);
    const uint32_t vs_base = smem_u32(&Vs[0][0][0]);
    constexpr uint32_t STAGE = 64 * 72 * 2;   // 9216 B

    // per-lane ldmatrix offsets (bytes)
    const uint32_t klane = (uint32_t)(((lane >> 4) * 8 + (lane & 7)) * 144
                                      + ((lane >> 3) & 1) * 16);
    const uint32_t vlane = (uint32_t)((lane & 15) * 144 + (lane >> 4) * 16);

    // cp.async tile loader: K + V, one group
    const int lr = tid >> 3, lch = (tid & 7) * 8;
    auto load_tile = [&](int j0, int buf) {
        #pragma unroll
        for (int j = 0; j < 2; j++) {
            const int r = lr + j * 32;
            const __half* kp = base + (long long)(j0 + r) * rowstride;
            cp16(ks_base + buf * STAGE + (uint32_t)(r * 144 + lch * 2), kp + lch);
            cp16(vs_base + buf * STAGE + (uint32_t)(r * 144 + lch * 2), kp + 128 + lch);
        }
        cp_commit();
    };

    float acc[8][4];
    #pragma unroll
    for (int nt = 0; nt < 8; nt++)
        #pragma unroll
        for (int i = 0; i < 4; i++) acc[nt][i] = 0.f;
    float m0v = -1e30f, m1v = -1e30f, l0 = 0.f, l1 = 0.f;

    load_tile(0, 0);

    for (int it = 0; it < TT / 64; ++it) {
        const int buf = it & 1;
        cp_wait<0>();
        __syncthreads();
        if (it + 1 < TT / 64) load_tile((it + 1) * 64, buf ^ 1);

        const uint32_t kb = ks_base + buf * STAGE + klane;
        const uint32_t vb = vs_base + buf * STAGE + vlane;

        // S = (Q/8) @ K^T
        float s[8][4];
        #pragma unroll
        for (int np = 0; np < 4; np++) {
            s[2*np][0] = s[2*np][1] = s[2*np][2] = s[2*np][3] = 0.f;
            s[2*np+1][0] = s[2*np+1][1] = s[2*np+1][2] = s[2*np+1][3] = 0.f;
            #pragma unroll
            for (int kk = 0; kk < 4; kk++) {
                uint32_t r0, r1, r2, r3;
                ldm_x4(r0, r1, r2, r3, kb + (uint32_t)(np * 16 * 144 + kk * 32));
                mma_f16(s[2*np],     qf[kk], r0, r1, s[2*np]);
                mma_f16(s[2*np+1],   qf[kk], r2, r3, s[2*np+1]);
            }
        }

        // online softmax (rows g / g+8; quad reduction)
        float rmax0 = -1e30f, rmax1 = -1e30f;
        #pragma unroll
        for (int nt = 0; nt < 8; nt++) {
            rmax0 = fmaxf(rmax0, fmaxf(s[nt][0], s[nt][1]));
            rmax1 = fmaxf(rmax1, fmaxf(s[nt][2], s[nt][3]));
        }
        rmax0 = fmaxf(rmax0, __shfl_xor_sync(0xffffffffu, rmax0, 1));
        rmax0 = fmaxf(rmax0, __shfl_xor_sync(0xffffffffu, rmax0, 2));
        rmax1 = fmaxf(rmax1, __shfl_xor_sync(0xffffffffu, rmax1, 1));
        rmax1 = fmaxf(rmax1, __shfl_xor_sync(0xffffffffu, rmax1, 2));

        float mn0 = fmaxf(m0v, rmax0), mn1 = fmaxf(m1v, rmax1);
        float c0 = __expf(m0v - mn0), c1 = __expf(m1v - mn1);
        m0v = mn0; m1v = mn1;

        float ps0 = 0.f, ps1 = 0.f;
        #pragma unroll
        for (int nt = 0; nt < 8; nt++) {
            s[nt][0] = __expf(s[nt][0] - mn0); ps0 += s[nt][0];
            s[nt][1] = __expf(s[nt][1] - mn0); ps0 += s[nt][1];
            s[nt][2] = __expf(s[nt][2] - mn1); ps1 += s[nt][2];
            s[nt][3] = __expf(s[nt][3] - mn1); ps1 += s[nt][3];
        }
        ps0 += __shfl_xor_sync(0xffffffffu, ps0, 1);
        ps0 += __shfl_xor_sync(0xffffffffu, ps0, 2);
        ps1 += __shfl_xor_sync(0xffffffffu, ps1, 1);
        ps1 += __shfl_xor_sync(0xffffffffu, ps1, 2);
        l0 = l0 * c0 + ps0;
        l1 = l1 * c1 + ps1;

        #pragma unroll
        for (int nt = 0; nt < 8; nt++) {
            acc[nt][0] *= c0; acc[nt][1] *= c0;
            acc[nt][2] *= c1; acc[nt][3] *= c1;
        }

        // P C-frag -> A-frag directly (keys become k of PV mma)
        uint32_t af[4][4];
        #pragma unroll
        for (int kk = 0; kk < 4; kk++) {
            af[kk][0] = pack2(s[2 * kk][0],     s[2 * kk][1]);
            af[kk][1] = pack2(s[2 * kk][2],     s[2 * kk][3]);
            af[kk][2] = pack2(s[2 * kk + 1][0], s[2 * kk + 1][1]);
            af[kk][3] = pack2(s[2 * kk + 1][2], s[2 * kk + 1][3]);
        }

        // acc += P @ V  (B-frags via ldmatrix.trans on raw V)
        #pragma unroll
        for (int np = 0; np < 4; np++) {
            #pragma unroll
            for (int kk = 0; kk < 4; kk++) {
                uint32_t r0, r1, r2, r3;
                ldm_x4_t(r0, r1, r2, r3, vb + (uint32_t)(kk * 16 * 144 + np * 32));
                mma_f16(acc[2*np],   af[kk], r0, r1, acc[2*np]);
                mma_f16(acc[2*np+1], af[kk], r2, r3, acc[2*np+1]);
            }
        }
        __syncthreads();
    }

    const float inv0 = 1.f / l0, inv1 = 1.f / l1;
    const long long o0 = (long long)(b * TT + q0 + g) * EMB + h * SS;
    const long long o1 = (long long)(b * TT + q0 + 8 + g) * EMB + h * SS;
    #pragma unroll
    for (int nt = 0; nt < 8; nt++) {
        *(uint32_t*)(res + o0 + nt * 8 + 2 * t4) = pack2(acc[nt][0] * inv0, acc[nt][1] * inv0);
        *(uint32_t*)(res + o1 + nt * 8 + 2 * t4) = pack2(acc[nt][2] * inv1, acc[nt][3] * inv1);
    }
}

// ---------------- fused residual + LayerNorm (+optional fp16 copy) ------
__global__ __launch_bounds__(256)
void ln_kernel(const float* __restrict__ X, const float* __restrict__ Y,
               const float* __restrict__ g, const float* __restrict__ bta,
               float* __restrict__ out, __half* __restrict__ oh)
{
    const int row = blockIdx.x;
    const int tid = threadIdx.x;
    const float* xr = X + (long long)row * EMB;
    const float* yr = Y + (long long)row * EMB;

    float v[4], s = 0.f, ss = 0.f;
    #pragma unroll
    for (int i = 0; i < 4; i++) {
        int c = tid + i * 256;
        float t = xr[c] + yr[c];
        v[i] = t;
        s += t;
        ss = fmaf(t, t, ss);
    }

    __shared__ float rs[8], rss[8];
    #pragma unroll
    for (int o = 16; o > 0; o >>= 1) {
        s  += __shfl_xor_sync(0xffffffffu, s,  o);
        ss += __shfl_xor_sync(0xffffffffu, ss, o);
    }
    const int warp = tid >> 5, lane = tid & 31;
    if (lane == 0) { rs[warp] = s; rss[warp] = ss; }
    __syncthreads();
    float ts = 0.f, tss = 0.f;
    #pragma unroll
    for (int i = 0; i < 8; i++) { ts += rs[i]; tss += rss[i]; }

    const float mean = ts * (1.0f / EMB);
    const float var  = tss * (1.0f / EMB) - mean * mean;
    const float rstd = rsqrtf(var + 1e-5f);

    #pragma unroll
    for (int i = 0; i < 4; i++) {
        int c = tid + i * 256;
        float o = (v[i] - mean) * rstd * g[c] + bta[c];
        if (out) out[(long long)row * EMB + c] = o;
        if (oh)  oh [(long long)row * EMB + c] = __float2half_rn(o);
    }
}

// ---------------- launch --------------------------------------------------
extern "C" void kernel_launch(void* const* d_in, const int* in_sizes, int n_in,
                              void* d_out, int out_size)
{
    const float* x     = (const float*)d_in[0];
    const float* Wkqv  = (const float*)d_in[1];
    const float* Wproj = (const float*)d_in[2];
    const float* g1    = (const float*)d_in[3];
    const float* b1    = (const float*)d_in[4];
    const float* W1    = (const float*)d_in[5];
    const float* bff1  = (const float*)d_in[6];
    const float* W2    = (const float*)d_in[7];
    const float* bff2  = (const float*)d_in[8];
    const float* g2    = (const float*)d_in[9];
    const float* b2    = (const float*)d_in[10];
    float* out = (float*)d_out;

    float *p_mha, *p_x1, *p_ff;
    __half *p_xh, *p_kqv, *p_res, *p_x1h, *p_hh, *p_Wkh, *p_Wph, *p_W1h, *p_W2h;
    cudaGetSymbolAddress((void**)&p_xh,  g_xh);
    cudaGetSymbolAddress((void**)&p_kqv, g_kqv);
    cudaGetSymbolAddress((void**)&p_res, g_res);
    cudaGetSymbolAddress((void**)&p_mha, g_mha);
    cudaGetSymbolAddress((void**)&p_x1,  g_x1);
    cudaGetSymbolAddress((void**)&p_x1h, g_x1h);
    cudaGetSymbolAddress((void**)&p_hh,  g_hh);
    cudaGetSymbolAddress((void**)&p_ff,  g_ff);
    cudaGetSymbolAddress((void**)&p_Wkh, g_Wkh);
    cudaGetSymbolAddress((void**)&p_Wph, g_Wph);
    cudaGetSymbolAddress((void**)&p_W1h, g_W1h);
    cudaGetSymbolAddress((void**)&p_W2h, g_W2h);

    // smem: 2 stages x (A 18432 + B 64*(BN+8)*2)
    constexpr int SM256 = 2 * (18432 + 64 * 264 * 2);  // 104448
    constexpr int SM64  = 2 * (18432 + 64 * 72  * 2);  // 55296
    cudaFuncSetAttribute(gemm_f16<256,0>, cudaFuncAttributeMaxDynamicSharedMemorySize, SM256);
    cudaFuncSetAttribute(gemm_f16<256,1>, cudaFuncAttributeMaxDynamicSharedMemorySize, SM256);
    cudaFuncSetAttribute(gemm_f16<256,2>, cudaFuncAttributeMaxDynamicSharedMemorySize, SM256);
    cudaFuncSetAttribute(gemm_f16<64,3>,  cudaFuncAttributeMaxDynamicSharedMemorySize, SM64);

    // 0) all f32->f16 conversions, one launch
    cvt_all<<<NB_X + NB_WK + NB_WP + NB_W1 + NB_W2, 256>>>(
        x, Wkqv, Wproj, W1, W2, p_xh, p_Wkh, p_Wph, p_W1h, p_W2h);

    // 1) kqv = xh @ Wkqv : [65536,64] @ [64,192] -> fp16
    gemm_f16<64, 3><<<dim3(192 / 64, (ROWS * HH) / 128), 128, SM64>>>(
        p_xh, p_Wkh, nullptr, nullptr, p_kqv, ROWS * HH, 192, SS);
    // 2) attention -> res (fp16)
    attn_f16<<<dim3(TT / 128, HH, BB), 256>>>(p_kqv, p_res);
    // 3) mha = res @ Wproj
    gemm_f16<256, 0><<<dim3(EMB / 256, ROWS / 128), 256, SM256>>>(
        p_res, p_Wph, nullptr, p_mha, nullptr, ROWS, EMB, EMB);
    // 4) x1 = LN(x + mha)  (+ fp16 copy)
    ln_kernel<<<ROWS, 256>>>(x, p_mha, g1, b1, p_x1, p_x1h);
    // 5) h = gelu(x1 @ W1 + bff1) -> fp16
    gemm_f16<256, 2><<<dim3(FF4 / 256, ROWS / 128), 256, SM256>>>(
        p_x1h, p_W1h, bff1, nullptr, p_hh, ROWS, FF4, EMB);
    // 6) ff = h @ W2 + bff2
    gemm_f16<256, 1><<<dim3(EMB / 256, ROWS / 128), 256, SM256>>>(
        p_hh, p_W2h, bff2, p_ff, nullptr, ROWS, EMB, FF4);
    // 7) out = LN(x1 + ff)
    ln_kernel<<<ROWS, 256>>>(p_x1, p_ff, g2, b2, out, nullptr);
}

// round 15
// speedup vs baseline: 1.0878x; 1.0878x over previous
#include <cuda_runtime.h>
#include <cuda_fp16.h>
#include <math.h>
#include <stdint.h>

// ---------------- problem constants ----------------
#define BB   2
#define TT   2048
#define HH   16
#define SS   64
#define EMB  1024          // HH*SS
#define ROWS (BB*TT)       // 4096
#define FF4  (4*EMB)       // 4096

// ---------------- scratch (device globals; no allocation) ----------------
__device__ __half g_xh [(long long)ROWS * EMB];      // x in fp16
__device__ __half g_kqv[(long long)ROWS * HH * 192]; // [B,T,H,192] (k|q|v) fp16
__device__ __half g_res[(long long)ROWS * EMB];      // attention out (fp16)
__device__ float  g_mha[(long long)ROWS * EMB];
__device__ float  g_x1 [(long long)ROWS * EMB];
__device__ __half g_x1h[(long long)ROWS * EMB];
__device__ __half g_hh [(long long)ROWS * FF4];
__device__ float  g_ff [(long long)ROWS * EMB];
// fp16 weights, k-major [K, N]
__device__ __half g_Wkh[(long long)SS * 192];
__device__ __half g_Wph[(long long)EMB * EMB];
__device__ __half g_W1h[(long long)EMB * FF4];
__device__ __half g_W2h[(long long)FF4 * EMB];

// ---------------- helpers ----------------
__device__ __forceinline__ float gelu_exact(float v) {
    return 0.5f * v * (1.0f + erff(v * 0.70710678118654752440f));
}
__device__ __forceinline__ void mma_f16(float (&d)[4], const uint32_t (&a)[4],
                                        const uint32_t b0, const uint32_t b1,
                                        const float (&c)[4]) {
    asm volatile(
        "mma.sync.aligned.m16n8k16.row.col.f32.f16.f16.f32 "
        "{%0,%1,%2,%3}, {%4,%5,%6,%7}, {%8,%9}, {%10,%11,%12,%13};\n"
        : "=f"(d[0]), "=f"(d[1]), "=f"(d[2]), "=f"(d[3])
        : "r"(a[0]), "r"(a[1]), "r"(a[2]), "r"(a[3]),
          "r"(b0), "r"(b1),
          "f"(c[0]), "f"(c[1]), "f"(c[2]), "f"(c[3]));
}
__device__ __forceinline__ uint32_t pack2(float lo, float hi) {
    __half2 h = __floats2half2_rn(lo, hi);
    return *(uint32_t*)&h;
}
__device__ __forceinline__ uint32_t smem_u32(const void* p) {
    uint32_t a;
    asm("{ .reg .u64 t; cvta.to.shared.u64 t, %1; cvt.u32.u64 %0, t; }" : "=r"(a) : "l"(p));
    return a;
}
__device__ __forceinline__ void cp16(uint32_t dst, const void* src) {
    asm volatile("cp.async.cg.shared.global [%0], [%1], 16;" :: "r"(dst), "l"(src));
}
__device__ __forceinline__ void cp_commit() {
    asm volatile("cp.async.commit_group;" ::: "memory");
}
template<int N>
__device__ __forceinline__ void cp_wait() {
    asm volatile("cp.async.wait_group %0;" :: "n"(N) : "memory");
}
__device__ __forceinline__ void ldm_x4(uint32_t& r0, uint32_t& r1, uint32_t& r2,
                                       uint32_t& r3, uint32_t addr) {
    asm volatile("ldmatrix.sync.aligned.m8n8.x4.shared.b16 {%0,%1,%2,%3}, [%4];"
                 : "=r"(r0), "=r"(r1), "=r"(r2), "=r"(r3) : "r"(addr));
}
__device__ __forceinline__ void ldm_x4_t(uint32_t& r0, uint32_t& r1, uint32_t& r2,
                                         uint32_t& r3, uint32_t addr) {
    asm volatile("ldmatrix.sync.aligned.m8n8.x4.trans.shared.b16 {%0,%1,%2,%3}, [%4];"
                 : "=r"(r0), "=r"(r1), "=r"(r2), "=r"(r3) : "r"(addr));
}

// ================= fp16 GEMM: 64x64 warp tiles, B k-major =================
// C[M,N] = A[M,K] @ B[K,N].  BM=128, BK=64, BN in {64,128}.
// 128 threads = 4 warps (2m x 2n); warp tile 64 x (BN/2).
// __launch_bounds__(128,3): 3 CTAs/SM (12 warps/SM) to feed the HMMA pipe.
// EPI: 0 = f32; 1 = +bias f32; 2 = +bias+gelu f16; 3 = plain f16.
template<int BN, int EPI>
__global__ __launch_bounds__(128, 3)
void gemm_f16(const __half* __restrict__ Ah, const __half* __restrict__ Bw,
              const float* __restrict__ bias,
              float* __restrict__ Cf, __half* __restrict__ Ch,
              int M, int N, int K)
{
    constexpr int BM = 128, BK = 64;
    constexpr int WN  = BN / 2;             // warp n-extent (64 or 32)
    constexpr int NT  = WN / 8;             // n8 tiles per warp (8 or 4)
    constexpr int NP  = NT / 2;             // 16-col pairs (4 or 2)
    constexpr int LDA = 72;                 // A row stride (halves)
    constexpr int LDB = BN + 8;             // B row stride (halves)
    constexpr int ABY = BM * LDA * 2;       // 18432
    constexpr int BBY = BK * LDB * 2;
    constexpr int STB = ABY + BBY;
    constexpr int CPR = BN / 8;             // B 16B-chunks per row

    extern __shared__ char smc[];
    const uint32_t sbase = smem_u32(smc);

    const int tid  = threadIdx.x;
    const int w    = tid >> 5;
    const int lane = tid & 31;
    const int g    = lane >> 2;
    const int t4   = lane & 3;
    const int wm   = w >> 1;                // 0..1
    const int wn   = w & 1;                 // 0..1
    const int m0   = blockIdx.y * BM;
    const int n0   = blockIdx.x * BN;

    float acc[4][NT][4];
    #pragma unroll
    for (int mt = 0; mt < 4; mt++)
        #pragma unroll
        for (int nt = 0; nt < NT; nt++)
            #pragma unroll
            for (int i = 0; i < 4; i++) acc[mt][nt][i] = 0.f;

    const int nk = K >> 6;   // BK=64 slabs

    auto load_slab = [&](int kt, int st) {
        const uint32_t sa = sbase + (uint32_t)st * STB;
        #pragma unroll
        for (int i = 0; i < 8; i++) {                 // A: 1024 chunks / 128 thr
            int ci = tid + i * 128;
            int r = ci >> 3, c = (ci & 7) * 8;
            cp16(sa + (uint32_t)(r * LDA + c) * 2,
                 Ah + (long long)(m0 + r) * K + kt * 64 + c);
        }
        const uint32_t sb = sa + ABY;
        #pragma unroll
        for (int i = 0; i < (BK * CPR) / 128; i++) {  // B: k-major rows of W
            int ci = tid + i * 128;
            int r = ci / CPR, c = (ci % CPR) * 8;
            cp16(sb + (uint32_t)(r * LDB + c) * 2,
                 Bw + (long long)(kt * 64 + r) * N + n0 + c);
        }
        cp_commit();
    };

    // per-lane ldmatrix base offsets (bytes)
    const uint32_t aoff = (uint32_t)((wm * 64 + (lane & 15)) * LDA + (lane >> 4) * 8) * 2;
    const uint32_t boff = (uint32_t)((lane & 15) * LDB * 2 + (lane >> 4) * 16 + wn * WN * 2);

    load_slab(0, 0);

    for (int kt = 0; kt < nk; ++kt) {
        cp_wait<0>();
        __syncthreads();
        if (kt + 1 < nk) load_slab(kt + 1, (kt + 1) & 1);

        const uint32_t sa = sbase + (uint32_t)(kt & 1) * STB;
        const uint32_t sb = sa + ABY;
        #pragma unroll
        for (int ks = 0; ks < 4; ks++) {
            uint32_t a[4][4];
            #pragma unroll
            for (int mt = 0; mt < 4; mt++)
                ldm_x4(a[mt][0], a[mt][1], a[mt][2], a[mt][3],
                       sa + aoff + (uint32_t)(mt * (16 * LDA * 2) + ks * 32));
            #pragma unroll
            for (int np = 0; np < NP; np++) {
                uint32_t r0, r1, r2, r3;
                ldm_x4_t(r0, r1, r2, r3,
                         sb + boff + (uint32_t)(ks * (16 * LDB * 2) + np * 32));
                #pragma unroll
                for (int mt = 0; mt < 4; mt++) {
                    mma_f16(acc[mt][2 * np],     a[mt], r0, r1, acc[mt][2 * np]);
                    mma_f16(acc[mt][2 * np + 1], a[mt], r2, r3, acc[mt][2 * np + 1]);
                }
            }
        }
    }

    // epilogue
    #pragma unroll
    for (int mt = 0; mt < 4; mt++) {
        int row = m0 + wm * 64 + mt * 16 + g;
        #pragma unroll
        for (int nt = 0; nt < NT; nt++) {
            int col = n0 + wn * WN + nt * 8 + 2 * t4;
            float v00 = acc[mt][nt][0], v01 = acc[mt][nt][1];
            float v10 = acc[mt][nt][2], v11 = acc[mt][nt][3];
            if (EPI == 1 || EPI == 2) {
                float b0 = bias[col], b1 = bias[col + 1];
                v00 += b0; v01 += b1; v10 += b0; v11 += b1;
            }
            if (EPI == 2) {
                v00 = gelu_exact(v00); v01 = gelu_exact(v01);
                v10 = gelu_exact(v10); v11 = gelu_exact(v11);
            }
            const long long o0 = (long long)row * N + col;
            const long long o1 = (long long)(row + 8) * N + col;
            if (EPI == 2 || EPI == 3) {
                *(uint32_t*)(Ch + o0) = pack2(v00, v01);
                *(uint32_t*)(Ch + o1) = pack2(v10, v11);
            } else {
                *(float2*)(Cf + o0) = make_float2(v00, v01);
                *(float2*)(Cf + o1) = make_float2(v10, v11);
            }
        }
    }
}

// ============ fused f32 -> fp16 conversions (one launch for all) ============
#define NB_X  ((ROWS * EMB) / 1024)        // 4096
#define NB_WK ((SS * 192) / 1024)          // 12
#define NB_WP ((EMB * EMB) / 1024)         // 1024
#define NB_W1 ((EMB * FF4) / 1024)         // 4096
#define NB_W2 ((FF4 * EMB) / 1024)         // 4096
__global__ __launch_bounds__(256)
void cvt_all(const float* __restrict__ x, const float* __restrict__ Wk,
             const float* __restrict__ Wp, const float* __restrict__ W1,
             const float* __restrict__ W2,
             __half* __restrict__ xh, __half* __restrict__ Wkh,
             __half* __restrict__ Wph, __half* __restrict__ W1h,
             __half* __restrict__ W2h)
{
    int blk = blockIdx.x;
    const float* src; __half* dst;
    if      (blk < NB_X)                         { src = x;  dst = xh; }
    else if ((blk -= NB_X)  < NB_WK)             { src = Wk; dst = Wkh; }
    else if ((blk -= NB_WK) < NB_WP)             { src = Wp; dst = Wph; }
    else if ((blk -= NB_WP) < NB_W1)             { src = W1; dst = W1h; }
    else    { blk -= NB_W1;                        src = W2; dst = W2h; }
    const long long i = ((long long)blk * 256 + threadIdx.x) * 4;
    float4 v = *(const float4*)(src + i);
    __half h[4] = {__float2half_rn(v.x), __float2half_rn(v.y),
                   __float2half_rn(v.z), __float2half_rn(v.w)};
    *(uint2*)(dst + i) = *(uint2*)h;
}

// ================= fp16 flash attention: cp.async + ldmatrix =================
// grid (T/128, H, B), 256 threads = 8 warps; warp w owns 16 query rows.
__global__ __launch_bounds__(256)
void attn_f16(const __half* __restrict__ kqv, __half* __restrict__ res)
{
    __shared__ __half Ks[2][64][72];   // [key][dim]
    __shared__ __half Vs[2][64][72];   // [key][dim] raw; transposed via ldmatrix.trans

    const int tid  = threadIdx.x;
    const int w    = tid >> 5;
    const int lane = tid & 31;
    const int g    = lane >> 2;
    const int t4   = lane & 3;
    const int b    = blockIdx.z;
    const int h    = blockIdx.y;
    const int q0   = blockIdx.x * 128 + w * 16;

    const long long rowstride = (long long)HH * 192;
    const __half* base = kqv + ((long long)b * TT * HH + h) * 192;

    // Q A-frags, pre-scaled by 1/sqrt(S) = 0.125 (exact in fp16)
    uint32_t qf[4][4];
    {
        const __half2 sc = __float2half2_rn(0.125f);
        const __half* qp0 = base + (long long)(q0 + g)     * rowstride + 64;
        const __half* qp1 = base + (long long)(q0 + 8 + g) * rowstride + 64;
        #pragma unroll
        for (int kk = 0; kk < 4; kk++) {
            __half2 v0 = __hmul2(*(const __half2*)(qp0 + kk * 16 + 2 * t4), sc);
            __half2 v1 = __hmul2(*(const __half2*)(qp1 + kk * 16 + 2 * t4), sc);
            __half2 v2 = __hmul2(*(const __half2*)(qp0 + kk * 16 + 2 * t4 + 8), sc);
            __half2 v3 = __hmul2(*(const __half2*)(qp1 + kk * 16 + 2 * t4 + 8), sc);
            qf[kk][0] = *(uint32_t*)&v0; qf[kk][1] = *(uint32_t*)&v1;
            qf[kk][2] = *(uint32_t*)&v2; qf[kk][3] = *(uint32_t*)&v3;
        }
    }

    const uint32_t ks_base = smem_u32(&Ks[0][0][0]);
    const uint32_t vs_base = smem_u32(&Vs[0][0][0]);
    constexpr uint32_t STAGE = 64 * 72 * 2;   // 9216 B

    // per-lane ldmatrix offsets (bytes)
    const uint32_t klane = (uint32_t)(((lane >> 4) * 8 + (lane & 7)) * 144
                                      + ((lane >> 3) & 1) * 16);
    const uint32_t vlane = (uint32_t)((lane & 15) * 144 + (lane >> 4) * 16);

    // cp.async tile loader: K + V, one group
    const int lr = tid >> 3, lch = (tid & 7) * 8;
    auto load_tile = [&](int j0, int buf) {
        #pragma unroll
        for (int j = 0; j < 2; j++) {
            const int r = lr + j * 32;
            const __half* kp = base + (long long)(j0 + r) * rowstride;
            cp16(ks_base + buf * STAGE + (uint32_t)(r * 144 + lch * 2), kp + lch);
            cp16(vs_base + buf * STAGE + (uint32_t)(r * 144 + lch * 2), kp + 128 + lch);
        }
        cp_commit();
    };

    float acc[8][4];
    #pragma unroll
    for (int nt = 0; nt < 8; nt++)
        #pragma unroll
        for (int i = 0; i < 4; i++) acc[nt][i] = 0.f;
    float m0v = -1e30f, m1v = -1e30f, l0 = 0.f, l1 = 0.f;

    load_tile(0, 0);

    for (int it = 0; it < TT / 64; ++it) {
        const int buf = it & 1;
        cp_wait<0>();
        __syncthreads();
        if (it + 1 < TT / 64) load_tile((it + 1) * 64, buf ^ 1);

        const uint32_t kb = ks_base + buf * STAGE + klane;
        const uint32_t vb = vs_base + buf * STAGE + vlane;

        // S = (Q/8) @ K^T
        float s[8][4];
        #pragma unroll
        for (int np = 0; np < 4; np++) {
            s[2*np][0] = s[2*np][1] = s[2*np][2] = s[2*np][3] = 0.f;
            s[2*np+1][0] = s[2*np+1][1] = s[2*np+1][2] = s[2*np+1][3] = 0.f;
            #pragma unroll
            for (int kk = 0; kk < 4; kk++) {
                uint32_t r0, r1, r2, r3;
                ldm_x4(r0, r1, r2, r3, kb + (uint32_t)(np * 16 * 144 + kk * 32));
                mma_f16(s[2*np],     qf[kk], r0, r1, s[2*np]);
                mma_f16(s[2*np+1],   qf[kk], r2, r3, s[2*np+1]);
            }
        }

        // online softmax (rows g / g+8; quad reduction)
        float rmax0 = -1e30f, rmax1 = -1e30f;
        #pragma unroll
        for (int nt = 0; nt < 8; nt++) {
            rmax0 = fmaxf(rmax0, fmaxf(s[nt][0], s[nt][1]));
            rmax1 = fmaxf(rmax1, fmaxf(s[nt][2], s[nt][3]));
        }
        rmax0 = fmaxf(rmax0, __shfl_xor_sync(0xffffffffu, rmax0, 1));
        rmax0 = fmaxf(rmax0, __shfl_xor_sync(0xffffffffu, rmax0, 2));
        rmax1 = fmaxf(rmax1, __shfl_xor_sync(0xffffffffu, rmax1, 1));
        rmax1 = fmaxf(rmax1, __shfl_xor_sync(0xffffffffu, rmax1, 2));

        float mn0 = fmaxf(m0v, rmax0), mn1 = fmaxf(m1v, rmax1);
        float c0 = __expf(m0v - mn0), c1 = __expf(m1v - mn1);
        m0v = mn0; m1v = mn1;

        float ps0 = 0.f, ps1 = 0.f;
        #pragma unroll
        for (int nt = 0; nt < 8; nt++) {
            s[nt][0] = __expf(s[nt][0] - mn0); ps0 += s[nt][0];
            s[nt][1] = __expf(s[nt][1] - mn0); ps0 += s[nt][1];
            s[nt][2] = __expf(s[nt][2] - mn1); ps1 += s[nt][2];
            s[nt][3] = __expf(s[nt][3] - mn1); ps1 += s[nt][3];
        }
        ps0 += __shfl_xor_sync(0xffffffffu, ps0, 1);
        ps0 += __shfl_xor_sync(0xffffffffu, ps0, 2);
        ps1 += __shfl_xor_sync(0xffffffffu, ps1, 1);
        ps1 += __shfl_xor_sync(0xffffffffu, ps1, 2);
        l0 = l0 * c0 + ps0;
        l1 = l1 * c1 + ps1;

        #pragma unroll
        for (int nt = 0; nt < 8; nt++) {
            acc[nt][0] *= c0; acc[nt][1] *= c0;
            acc[nt][2] *= c1; acc[nt][3] *= c1;
        }

        // P C-frag -> A-frag directly (keys become k of PV mma)
        uint32_t af[4][4];
        #pragma unroll
        for (int kk = 0; kk < 4; kk++) {
            af[kk][0] = pack2(s[2 * kk][0],     s[2 * kk][1]);
            af[kk][1] = pack2(s[2 * kk][2],     s[2 * kk][3]);
            af[kk][2] = pack2(s[2 * kk + 1][0], s[2 * kk + 1][1]);
            af[kk][3] = pack2(s[2 * kk + 1][2], s[2 * kk + 1][3]);
        }

        // acc += P @ V  (B-frags via ldmatrix.trans on raw V)
        #pragma unroll
        for (int np = 0; np < 4; np++) {
            #pragma unroll
            for (int kk = 0; kk < 4; kk++) {
                uint32_t r0, r1, r2, r3;
                ldm_x4_t(r0, r1, r2, r3, vb + (uint32_t)(kk * 16 * 144 + np * 32));
                mma_f16(acc[2*np],   af[kk], r0, r1, acc[2*np]);
                mma_f16(acc[2*np+1], af[kk], r2, r3, acc[2*np+1]);
            }
        }
        __syncthreads();
    }

    const float inv0 = 1.f / l0, inv1 = 1.f / l1;
    const long long o0 = (long long)(b * TT + q0 + g) * EMB + h * SS;
    const long long o1 = (long long)(b * TT + q0 + 8 + g) * EMB + h * SS;
    #pragma unroll
    for (int nt = 0; nt < 8; nt++) {
        *(uint32_t*)(res + o0 + nt * 8 + 2 * t4) = pack2(acc[nt][0] * inv0, acc[nt][1] * inv0);
        *(uint32_t*)(res + o1 + nt * 8 + 2 * t4) = pack2(acc[nt][2] * inv1, acc[nt][3] * inv1);
    }
}

// ---------------- fused residual + LayerNorm (+optional fp16 copy) ------
__global__ __launch_bounds__(256)
void ln_kernel(const float* __restrict__ X, const float* __restrict__ Y,
               const float* __restrict__ g, const float* __restrict__ bta,
               float* __restrict__ out, __half* __restrict__ oh)
{
    const int row = blockIdx.x;
    const int tid = threadIdx.x;
    const float* xr = X + (long long)row * EMB;
    const float* yr = Y + (long long)row * EMB;

    float v[4], s = 0.f, ss = 0.f;
    #pragma unroll
    for (int i = 0; i < 4; i++) {
        int c = tid + i * 256;
        float t = xr[c] + yr[c];
        v[i] = t;
        s += t;
        ss = fmaf(t, t, ss);
    }

    __shared__ float rs[8], rss[8];
    #pragma unroll
    for (int o = 16; o > 0; o >>= 1) {
        s  += __shfl_xor_sync(0xffffffffu, s,  o);
        ss += __shfl_xor_sync(0xffffffffu, ss, o);
    }
    const int warp = tid >> 5, lane = tid & 31;
    if (lane == 0) { rs[warp] = s; rss[warp] = ss; }
    __syncthreads();
    float ts = 0.f, tss = 0.f;
    #pragma unroll
    for (int i = 0; i < 8; i++) { ts += rs[i]; tss += rss[i]; }

    const float mean = ts * (1.0f / EMB);
    const float var  = tss * (1.0f / EMB) - mean * mean;
    const float rstd = rsqrtf(var + 1e-5f);

    #pragma unroll
    for (int i = 0; i < 4; i++) {
        int c = tid + i * 256;
        float o = (v[i] - mean) * rstd * g[c] + bta[c];
        if (out) out[(long long)row * EMB + c] = o;
        if (oh)  oh [(long long)row * EMB + c] = __float2half_rn(o);
    }
}

// ---------------- launch --------------------------------------------------
extern "C" void kernel_launch(void* const* d_in, const int* in_sizes, int n_in,
                              void* d_out, int out_size)
{
    const float* x     = (const float*)d_in[0];
    const float* Wkqv  = (const float*)d_in[1];
    const float* Wproj = (const float*)d_in[2];
    const float* g1    = (const float*)d_in[3];
    const float* b1    = (const float*)d_in[4];
    const float* W1    = (const float*)d_in[5];
    const float* bff1  = (const float*)d_in[6];
    const float* W2    = (const float*)d_in[7];
    const float* bff2  = (const float*)d_in[8];
    const float* g2    = (const float*)d_in[9];
    const float* b2    = (const float*)d_in[10];
    float* out = (float*)d_out;

    float *p_mha, *p_x1, *p_ff;
    __half *p_xh, *p_kqv, *p_res, *p_x1h, *p_hh, *p_Wkh, *p_Wph, *p_W1h, *p_W2h;
    cudaGetSymbolAddress((void**)&p_xh,  g_xh);
    cudaGetSymbolAddress((void**)&p_kqv, g_kqv);
    cudaGetSymbolAddress((void**)&p_res, g_res);
    cudaGetSymbolAddress((void**)&p_mha, g_mha);
    cudaGetSymbolAddress((void**)&p_x1,  g_x1);
    cudaGetSymbolAddress((void**)&p_x1h, g_x1h);
    cudaGetSymbolAddress((void**)&p_hh,  g_hh);
    cudaGetSymbolAddress((void**)&p_ff,  g_ff);
    cudaGetSymbolAddress((void**)&p_Wkh, g_Wkh);
    cudaGetSymbolAddress((void**)&p_Wph, g_Wph);
    cudaGetSymbolAddress((void**)&p_W1h, g_W1h);
    cudaGetSymbolAddress((void**)&p_W2h, g_W2h);

    // smem: 2 stages x (A 18432 + B 64*(BN+8)*2)
    constexpr int SM128 = 2 * (18432 + 64 * 136 * 2);  // 71680 -> 3 CTAs/SM
    constexpr int SM64  = 2 * (18432 + 64 * 72  * 2);  // 55296
    cudaFuncSetAttribute(gemm_f16<128,0>, cudaFuncAttributeMaxDynamicSharedMemorySize, SM128);
    cudaFuncSetAttribute(gemm_f16<128,1>, cudaFuncAttributeMaxDynamicSharedMemorySize, SM128);
    cudaFuncSetAttribute(gemm_f16<128,2>, cudaFuncAttributeMaxDynamicSharedMemorySize, SM128);
    cudaFuncSetAttribute(gemm_f16<64,3>,  cudaFuncAttributeMaxDynamicSharedMemorySize, SM64);

    // 0) all f32->f16 conversions, one launch
    cvt_all<<<NB_X + NB_WK + NB_WP + NB_W1 + NB_W2, 256>>>(
        x, Wkqv, Wproj, W1, W2, p_xh, p_Wkh, p_Wph, p_W1h, p_W2h);

    // 1) kqv = xh @ Wkqv : [65536,64] @ [64,192] -> fp16
    gemm_f16<64, 3><<<dim3(192 / 64, (ROWS * HH) / 128), 128, SM64>>>(
        p_xh, p_Wkh, nullptr, nullptr, p_kqv, ROWS * HH, 192, SS);
    // 2) attention -> res (fp16)
    attn_f16<<<dim3(TT / 128, HH, BB), 256>>>(p_kqv, p_res);
    // 3) mha = res @ Wproj
    gemm_f16<128, 0><<<dim3(EMB / 128, ROWS / 128), 128, SM128>>>(
        p_res, p_Wph, nullptr, p_mha, nullptr, ROWS, EMB, EMB);
    // 4) x1 = LN(x + mha)  (+ fp16 copy)
    ln_kernel<<<ROWS, 256>>>(x, p_mha, g1, b1, p_x1, p_x1h);
    // 5) h = gelu(x1 @ W1 + bff1) -> fp16
    gemm_f16<128, 2><<<dim3(FF4 / 128, ROWS / 128), 128, SM128>>>(
        p_x1h, p_W1h, bff1, nullptr, p_hh, ROWS, FF4, EMB);
    // 6) ff = h @ W2 + bff2
    gemm_f16<128, 1><<<dim3(EMB / 128, ROWS / 128), 128, SM128>>>(
        p_hh, p_W2h, bff2, p_ff, nullptr, ROWS, EMB, FF4);
    // 7) out = LN(x1 + ff)
    ln_kernel<<<ROWS, 256>>>(p_x1, p_ff, g2, b2, out, nullptr);
}